// round 1
// baseline (speedup 1.0000x reference)
#include <cuda_runtime.h>
#include <cuda_bf16.h>

#define FULL 0xffffffffu

constexpr int L = 16;

// One warp handles 2 batches: lanes 0-15 -> batch A states 0-15,
// lanes 16-31 -> batch B states 0-15. All shuffles use width=16.
//
// Forward recursion kept in scaled-linear domain:
//   s_j = exp(alpha_j - M),  s'_j = (sum_i s_i * expTrans[i][j]) * exp(x_t[j])
// with rescale by s_0 every 4 steps (M += log(s_0)).
// Emit + transition scores folded into the same loop (x read once).

__global__ __launch_bounds__(256) void crf_fwd_kernel(
    const float* __restrict__ x,      // [B, T, L]
    const float* __restrict__ trans,  // [L, L]
    const int*   __restrict__ label,  // [B, T]
    const int*   __restrict__ length, // [B]
    float*       __restrict__ out,    // [B]
    int B, int T)
{
    __shared__ float sE[L * L];   // exp(trans)
    __shared__ float sT[L * L];   // raw trans

    int tid = threadIdx.x;
    if (tid < L * L) {
        float tv = trans[tid];
        sT[tid] = tv;
        sE[tid] = __expf(tv);
    }
    __syncthreads();

    int warp = tid >> 5;
    int lane = tid & 31;
    int j    = lane & 15;                       // state index
    int b    = blockIdx.x * 16 + warp * 2 + (lane >> 4);
    if (b >= B) return;

    // Lane j holds column j of expTrans: Ereg[i] = exp(trans[i][j])
    float Ereg[L];
#pragma unroll
    for (int i = 0; i < L; ++i) Ereg[i] = sE[i * L + j];

    const float* xb = x + (size_t)b * T * L;
    const int*   lb = label + (size_t)b * T;
    int len = length[b];

    // ---- t = 0 init ----
    float x0   = xb[j];
    int   plab = lb[0];
    float point = __shfl_sync(FULL, x0, plab, L);  // x[b,0,label0]
    float tp    = 0.f;
    float s     = __expf(x0);   // alpha0 in linear domain
    float M     = 0.f;

    // warp-uniform trip count (both halves), predicated updates below
    int lenMax = max(len, __shfl_xor_sync(FULL, len, 16));

    // 4-deep prefetch pipeline for x_t row and label_t (reads clamped to T-1: always valid)
    int Tm1 = T - 1;
    float xp0, xp1, xp2, xp3;
    int   lp0, lp1, lp2, lp3;
    xp0 = xb[min(1, Tm1) * L + j];  lp0 = lb[min(1, Tm1)];
    xp1 = xb[min(2, Tm1) * L + j];  lp1 = lb[min(2, Tm1)];
    xp2 = xb[min(3, Tm1) * L + j];  lp2 = lb[min(3, Tm1)];
    xp3 = xb[min(4, Tm1) * L + j];  lp3 = lb[min(4, Tm1)];

#pragma unroll 4
    for (int t = 1; t < lenMax; ++t) {
        float xt = xp0; xp0 = xp1; xp1 = xp2; xp2 = xp3;
        int  lab = lp0; lp0 = lp1; lp1 = lp2; lp2 = lp3;
        int tn = min(t + 4, Tm1);
        xp3 = xb[tn * L + j];
        lp3 = lb[tn];

        float ex = __expf(xt);

        // 16x16 matvec: new_j = sum_i s_i * E[i][j]
        float p = s;
        float a0 = 0.f, a1 = 0.f, a2 = 0.f, a3 = 0.f;
#pragma unroll
        for (int i = 0; i < L; i += 4) {
            a0 = fmaf(__shfl_sync(FULL, p, i + 0, L), Ereg[i + 0], a0);
            a1 = fmaf(__shfl_sync(FULL, p, i + 1, L), Ereg[i + 1], a1);
            a2 = fmaf(__shfl_sync(FULL, p, i + 2, L), Ereg[i + 2], a2);
            a3 = fmaf(__shfl_sync(FULL, p, i + 3, L), Ereg[i + 3], a3);
        }
        float snew = ((a0 + a1) + (a2 + a3)) * ex;

        float ev = __shfl_sync(FULL, xt, lab, L);   // x[b,t,label_t]

        if (t < len) {
            s = snew;
            point += ev;
            tp += sT[plab * L + lab];
            plab = lab;
        }

        // periodic rescale to keep s in fp32 range
        if ((t & 3) == 0) {
            float r = __shfl_sync(FULL, s, 0, L);
            if (t < len) {
                M += __logf(r);
                s  = __fdividef(s, r);
            }
        }
    }

    // z = log(sum_j s_j) + M  over 16 states
    float sum = s;
#pragma unroll
    for (int o = 8; o >= 1; o >>= 1)
        sum += __shfl_xor_sync(FULL, sum, o, L);
    float z = __logf(sum) + M;

    if (j == 0) out[b] = z - (point + tp);
}

extern "C" void kernel_launch(void* const* d_in, const int* in_sizes, int n_in,
                              void* d_out, int out_size) {
    const float* x      = (const float*)d_in[0];
    const float* trans  = (const float*)d_in[1];
    const int*   label  = (const int*)d_in[2];
    const int*   length = (const int*)d_in[3];
    float*       out    = (float*)d_out;

    int B = in_sizes[3];                 // 4096
    int T = in_sizes[2] / B;             // 512

    int batchesPerBlock = 16;            // 8 warps x 2 batches
    int grid = (B + batchesPerBlock - 1) / batchesPerBlock;
    crf_fwd_kernel<<<grid, 256>>>(x, trans, label, length, out, B, T);
}

// round 2
// speedup vs baseline: 2.1228x; 2.1228x over previous
#include <cuda_runtime.h>

#define FULL 0xffffffffu
typedef unsigned long long u64;

constexpr int L = 16;
constexpr int DPRE = 8;        // x prefetch ring depth
constexpr float LOG2E = 1.4426950408889634f;
constexpr float LN2   = 0.6931471805599453f;

__device__ __forceinline__ u64 pk2(float lo, float hi) {
    u64 r; asm("mov.b64 %0,{%1,%2};" : "=l"(r) : "f"(lo), "f"(hi)); return r;
}
__device__ __forceinline__ void upk2(u64 v, float& lo, float& hi) {
    asm("mov.b64 {%0,%1},%2;" : "=f"(lo), "=f"(hi) : "l"(v));
}
__device__ __forceinline__ u64 fma2(u64 a, u64 b, u64 c) {
    u64 d; asm("fma.rn.f32x2 %0,%1,%2,%3;" : "=l"(d) : "l"(a), "l"(b), "l"(c)); return d;
}
__device__ __forceinline__ u64 mul2(u64 a, u64 b) {
    u64 d; asm("mul.rn.f32x2 %0,%1,%2;" : "=l"(d) : "l"(a), "l"(b)); return d;
}
__device__ __forceinline__ float ex2f(float v) {
    float r; asm("ex2.approx.f32 %0,%1;" : "=f"(r) : "f"(v)); return r;
}
// width-4 shuffle of a packed f32x2
__device__ __forceinline__ u64 shfl64_4(u64 v, int src) {
    unsigned lo = (unsigned)v, hi = (unsigned)(v >> 32);
    lo = __shfl_sync(FULL, lo, src, 4);
    hi = __shfl_sync(FULL, hi, src, 4);
    return ((u64)hi << 32) | lo;
}

// Block = 256 threads. Warps 0-3: recursion (8 batches each, 4 lanes/batch,
// 4 states/lane, scaled-linear domain with f32x2 packed matvec).
// Warps 4-7: emit+transition scores for the same 32 batches (gather-reduce).
__global__ __launch_bounds__(256, 1) void crf_kernel(
    const float* __restrict__ x,      // [B, T, L]
    const float* __restrict__ trans,  // [L, L]
    const int*   __restrict__ label,  // [B, T]
    const int*   __restrict__ length, // [B]
    float*       __restrict__ out,    // [B]
    int B, int T)
{
    __shared__ float sE[L * L];    // exp(trans)
    __shared__ float sT[L * L];    // raw trans
    __shared__ float sScore[32];   // emit+trans score per batch of this block

    int tid  = threadIdx.x;
    int lane = tid & 31;
    int w    = tid >> 5;

    if (tid < L * L) {
        float tv = trans[tid];
        sT[tid] = tv;
        sE[tid] = ex2f(tv * LOG2E);
    }
    __syncthreads();

    int blockBase = blockIdx.x * 32;

    if (w < 4) {
        // ------------------- recursion warps -------------------
        int g = lane >> 2;          // batch slot within warp (0..7)
        int c = lane & 3;           // state-group (owns states 4c..4c+3)
        int b = blockBase + w * 8 + g;
        if (b >= B) b = B - 1;      // safety (B divisible by 32 in practice)

        const float* xg = x + (size_t)b * T * L + c * 4;
        int len = length[b];

        int lenMax = len;
        lenMax = max(lenMax, __shfl_xor_sync(FULL, lenMax, 4));
        lenMax = max(lenMax, __shfl_xor_sync(FULL, lenMax, 8));
        lenMax = max(lenMax, __shfl_xor_sync(FULL, lenMax, 16));

        // E in registers, interleaved for the even/odd-i dual-accumulator trick:
        // EA0[q] = (E[2q][j0], E[2q+1][j1]),  EB0[q] = (E[2q][j1], E[2q+1][j0]), etc.
        int j0 = 4 * c, j1 = j0 + 1, j2 = j0 + 2, j3 = j0 + 3;
        u64 EA0[8], EB0[8], EA1[8], EB1[8];
#pragma unroll
        for (int q = 0; q < 8; ++q) {
            EA0[q] = pk2(sE[(2 * q) * L + j0], sE[(2 * q + 1) * L + j1]);
            EB0[q] = pk2(sE[(2 * q) * L + j1], sE[(2 * q + 1) * L + j0]);
            EA1[q] = pk2(sE[(2 * q) * L + j2], sE[(2 * q + 1) * L + j3]);
            EB1[q] = pk2(sE[(2 * q) * L + j3], sE[(2 * q + 1) * L + j2]);
        }

        // t=0 init: s_j = exp(x0_j), M = 0
        float4 x0 = *(const float4*)xg;
        u64 s01 = pk2(ex2f(x0.x * LOG2E), ex2f(x0.y * LOG2E));
        u64 s23 = pk2(ex2f(x0.z * LOG2E), ex2f(x0.w * LOG2E));
        float M = 0.f;

        // prefetch ring (addresses clamped to len-1 -> tail re-reads hit L1)
        float4 xv[DPRE];
#pragma unroll
        for (int d = 0; d < DPRE; ++d) {
            int tn = min(1 + d, len - 1);
            xv[d] = *(const float4*)(xg + (size_t)tn * L);
        }

        const u64 L2E2 = pk2(LOG2E, LOG2E);

#pragma unroll 4
        for (int t = 1; t < lenMax; ++t) {
            float4 xt = xv[0];
#pragma unroll
            for (int d = 0; d < DPRE - 1; ++d) xv[d] = xv[d + 1];
            {
                int tn = min(t + DPRE, len - 1);
                xv[DPRE - 1] = *(const float4*)(xg + (size_t)tn * L);
            }

            // e^{x_t} for own 4 states
            u64 a01 = mul2(pk2(xt.x, xt.y), L2E2);
            u64 a23 = mul2(pk2(xt.z, xt.w), L2E2);
            float f0, f1, f2, f3;
            upk2(a01, f0, f1); upk2(a23, f2, f3);
            float e0 = ex2f(f0), e1 = ex2f(f1), e2 = ex2f(f2), e3 = ex2f(f3);

            // gather all 16 s values as packed pairs v[q] = (s_{2q}, s_{2q+1})
            u64 v[8];
#pragma unroll
            for (int m = 0; m < 4; ++m) {
                v[2 * m]     = shfl64_4(s01, m);
                v[2 * m + 1] = shfl64_4(s23, m);
            }

            // dual accumulators: out_j = Sum_i s_i * E[i][j]
            u64 aA0 = 0, aB0 = 0, aA1 = 0, aB1 = 0;
#pragma unroll
            for (int q = 0; q < 8; ++q) {
                aA0 = fma2(v[q], EA0[q], aA0);
                aB0 = fma2(v[q], EB0[q], aB0);
                aA1 = fma2(v[q], EA1[q], aA1);
                aB1 = fma2(v[q], EB1[q], aB1);
            }
            float A0l, A0h, B0l, B0h, A1l, A1h, B1l, B1h;
            upk2(aA0, A0l, A0h); upk2(aB0, B0l, B0h);
            upk2(aA1, A1l, A1h); upk2(aB1, B1l, B1h);

            u64 n01 = mul2(pk2(A0l + B0h, B0l + A0h), pk2(e0, e1));
            u64 n23 = mul2(pk2(A1l + B1h, B1l + A1h), pk2(e2, e3));

            bool act = t < len;
            if (act) { s01 = n01; s23 = n23; }

            if ((t & 3) == 0) {        // cheap exponent-only rescale
                u64 p0 = shfl64_4(s01, 0);
                float s0, sdum; upk2(p0, s0, sdum);
                int k = (__float_as_int(s0) >> 23) - 127;
                if (act) {
                    M += (float)k * LN2;
                    float sc = __int_as_float((127 - k) << 23);  // 2^-k
                    u64 sc2 = pk2(sc, sc);
                    s01 = mul2(s01, sc2);
                    s23 = mul2(s23, sc2);
                }
            }
        }

        // z = log(sum_j s_j) + M
        float l0, l1, l2, l3;
        upk2(s01, l0, l1); upk2(s23, l2, l3);
        float sm = (l0 + l1) + (l2 + l3);
        sm += __shfl_xor_sync(FULL, sm, 1, 4);
        sm += __shfl_xor_sync(FULL, sm, 2, 4);
        float z = __logf(sm) + M;

        __syncthreads();   // wait for emit warps' sScore
        if (c == 0) out[b] = z - sScore[w * 8 + g];
    } else {
        // ------------------- emit/transition warps -------------------
        int we = w - 4;
#pragma unroll 1
        for (int k = 0; k < 8; ++k) {
            int b = blockBase + we * 8 + k;
            if (b >= B) b = B - 1;
            const int*   lb = label + (size_t)b * T;
            const float* xb = x + (size_t)b * T * L;
            int len = length[b];

            float acc = 0.f;
            for (int t = lane; t < len; t += 32) {
                int lab = lb[t];
                acc += xb[t * L + lab];                  // emit score
                if (t >= 1) acc += sT[lb[t - 1] * L + lab];  // transition score
            }
            acc += __shfl_xor_sync(FULL, acc, 16);
            acc += __shfl_xor_sync(FULL, acc, 8);
            acc += __shfl_xor_sync(FULL, acc, 4);
            acc += __shfl_xor_sync(FULL, acc, 2);
            acc += __shfl_xor_sync(FULL, acc, 1);
            if (lane == 0) sScore[we * 8 + k] = acc;
        }
        __syncthreads();
    }
}

extern "C" void kernel_launch(void* const* d_in, const int* in_sizes, int n_in,
                              void* d_out, int out_size) {
    const float* x      = (const float*)d_in[0];
    const float* trans  = (const float*)d_in[1];
    const int*   label  = (const int*)d_in[2];
    const int*   length = (const int*)d_in[3];
    float*       out    = (float*)d_out;

    int B = in_sizes[3];                 // 4096
    int T = in_sizes[2] / B;             // 512

    int grid = (B + 31) / 32;            // 32 batches per block
    crf_kernel<<<grid, 256>>>(x, trans, label, length, out, B, T);
}

// round 3
// speedup vs baseline: 2.2020x; 1.0373x over previous
#include <cuda_runtime.h>

#define FULL 0xffffffffu
typedef unsigned long long u64;

constexpr int L = 16;
constexpr int DPRE = 8;
constexpr float LOG2E = 1.4426950408889634f;
constexpr float LN2   = 0.6931471805599453f;

__device__ __forceinline__ u64 pk2(float lo, float hi) {
    u64 r; asm("mov.b64 %0,{%1,%2};" : "=l"(r) : "f"(lo), "f"(hi)); return r;
}
__device__ __forceinline__ void upk2(u64 v, float& lo, float& hi) {
    asm("mov.b64 {%0,%1},%2;" : "=f"(lo), "=f"(hi) : "l"(v));
}
__device__ __forceinline__ u64 fma2(u64 a, u64 b, u64 c) {
    u64 d; asm("fma.rn.f32x2 %0,%1,%2,%3;" : "=l"(d) : "l"(a), "l"(b), "l"(c)); return d;
}
__device__ __forceinline__ u64 mul2(u64 a, u64 b) {
    u64 d; asm("mul.rn.f32x2 %0,%1,%2;" : "=l"(d) : "l"(a), "l"(b)); return d;
}
__device__ __forceinline__ float ex2f(float v) {
    float r; asm("ex2.approx.f32 %0,%1;" : "=f"(r) : "f"(v)); return r;
}
__device__ __forceinline__ float hadd2(u64 v) {
    float lo, hi; upk2(v, lo, hi); return lo + hi;
}
__device__ __forceinline__ u64 shfl64_4(u64 v, int src) {
    unsigned lo = (unsigned)v, hi = (unsigned)(v >> 32);
    lo = __shfl_sync(FULL, lo, src, 4);
    hi = __shfl_sync(FULL, hi, src, 4);
    return ((u64)hi << 32) | lo;
}

// One half-recursion (fwd or bwd) over one batch, 4 lanes/batch, 4 states/lane.
// FWD:  s' = (s E) .* exp(x_t),  rows ascending from 1, cnt = m
// BWD:  w' = E (exp(x_t) .* w),  rows descending from len-1, cnt = len-1-m
// P layout: FWD  P[cc][q] = (E[2q][j0+cc], E[2q+1][j0+cc])   (column pairs)
//           BWD  P[rr][q] = (E[i0+rr][2q], E[i0+rr][2q+1])   (row pairs)
template <bool FWD>
__device__ __forceinline__ void half_recursion(
    const float* __restrict__ xg,   // batch base + c*4
    const u64 (&P)[4][8],
    int cnt, int baseRow, int kMax,
    u64& s01, u64& s23, float& M)
{
    int cntm1 = max(cnt - 1, 0);
    const int dir = FWD ? 1 : -1;

    float4 xv[DPRE];
#pragma unroll
    for (int d = 0; d < DPRE; ++d) {
        int kk = min(d, cntm1);
        xv[d] = *(const float4*)(xg + (size_t)(baseRow + dir * kk) * L);
    }

#pragma unroll 4
    for (int k = 0; k < kMax; ++k) {
        float4 xt = xv[0];
#pragma unroll
        for (int d = 0; d < DPRE - 1; ++d) xv[d] = xv[d + 1];
        {
            int kk = min(k + DPRE, cntm1);
            xv[DPRE - 1] = *(const float4*)(xg + (size_t)(baseRow + dir * kk) * L);
        }

        float e0 = ex2f(xt.x * LOG2E), e1 = ex2f(xt.y * LOG2E);
        float e2 = ex2f(xt.z * LOG2E), e3 = ex2f(xt.w * LOG2E);

        u64 m01, m23;
        if (FWD) { m01 = s01; m23 = s23; }
        else     { m01 = mul2(s01, pk2(e0, e1)); m23 = mul2(s23, pk2(e2, e3)); }

        // gather all 16 values as pairs v[q] = (u_2q, u_2q+1)
        u64 v[8];
#pragma unroll
        for (int g4 = 0; g4 < 4; ++g4) {
            v[2 * g4]     = shfl64_4(m01, g4);
            v[2 * g4 + 1] = shfl64_4(m23, g4);
        }

        u64 a0 = 0, a1 = 0, a2 = 0, a3 = 0;
#pragma unroll
        for (int q = 0; q < 8; ++q) {
            a0 = fma2(v[q], P[0][q], a0);
            a1 = fma2(v[q], P[1][q], a1);
            a2 = fma2(v[q], P[2][q], a2);
            a3 = fma2(v[q], P[3][q], a3);
        }
        float o0 = hadd2(a0), o1 = hadd2(a1), o2 = hadd2(a2), o3 = hadd2(a3);
        if (FWD) { o0 *= e0; o1 *= e1; o2 *= e2; o3 *= e3; }
        u64 n01 = pk2(o0, o1), n23 = pk2(o2, o3);

        bool act = k < cnt;
        if (act) { s01 = n01; s23 = n23; }

        if ((k & 3) == 3) {   // exponent-only rescale by state-0's magnitude
            u64 p0 = shfl64_4(s01, 0);
            float s0, sd; upk2(p0, s0, sd);
            int e = (__float_as_int(s0) >> 23) - 127;
            if (act) {
                M += (float)e * LN2;
                float sc = __int_as_float((127 - e) << 23);   // 2^-e
                u64 sc2 = pk2(sc, sc);
                s01 = mul2(s01, sc2);
                s23 = mul2(s23, sc2);
            }
        }
    }
}

// Block = 384 threads = 12 warps handling 32 batches:
//  warps 0-3 : forward half-recursions  (8 batches each, 4 lanes/batch)
//  warps 4-7 : backward half-recursions (same 8 batches), then combine+write
//  warps 8-11: emit + transition scores
__global__ __launch_bounds__(384, 1) void crf_kernel(
    const float* __restrict__ x,      // [B, T, L]
    const float* __restrict__ trans,  // [L, L]
    const int*   __restrict__ label,  // [B, T]
    const int*   __restrict__ length, // [B]
    float*       __restrict__ out,    // [B]
    int B, int T)
{
    __shared__ float sE[L * L];
    __shared__ float sT[L * L];
    __shared__ float sScore[32];
    __shared__ u64   sF01[32], sF23[32];
    __shared__ float sMf[32];

    int tid  = threadIdx.x;
    int lane = tid & 31;
    int w    = tid >> 5;

    if (tid < L * L) {
        float tv = trans[tid];
        sT[tid] = tv;
        sE[tid] = ex2f(tv * LOG2E);
    }
    __syncthreads();

    int blockBase = blockIdx.x * 32;

    if (w < 8) {
        bool isFwd = w < 4;
        int wb   = isFwd ? w : w - 4;
        int g    = lane >> 2;
        int c    = lane & 3;
        int slot = wb * 8 + g;
        int b    = min(blockBase + slot, B - 1);

        const float* xg = x + (size_t)b * T * L + c * 4;
        int len = length[b];
        int m   = (len - 1) >> 1;

        int cnt     = isFwd ? m : (len - 1 - m);
        int baseRow = isFwd ? 1 : (len - 1);

        int kMax = cnt;
        kMax = max(kMax, __shfl_xor_sync(FULL, kMax, 4));
        kMax = max(kMax, __shfl_xor_sync(FULL, kMax, 8));
        kMax = max(kMax, __shfl_xor_sync(FULL, kMax, 16));

        u64 P[4][8];
        u64 s01, s23;
        float M = 0.f;

        if (isFwd) {
            int j0 = 4 * c;
#pragma unroll
            for (int cc = 0; cc < 4; ++cc)
#pragma unroll
                for (int q = 0; q < 8; ++q)
                    P[cc][q] = pk2(sE[(2 * q) * L + j0 + cc],
                                   sE[(2 * q + 1) * L + j0 + cc]);
            float4 x0 = *(const float4*)xg;
            s01 = pk2(ex2f(x0.x * LOG2E), ex2f(x0.y * LOG2E));
            s23 = pk2(ex2f(x0.z * LOG2E), ex2f(x0.w * LOG2E));
            half_recursion<true>(xg, P, cnt, baseRow, kMax, s01, s23, M);
            sF01[slot] = s01; sF23[slot] = s23; sMf[slot] = M;
        } else {
            int i0 = 4 * c;
#pragma unroll
            for (int rr = 0; rr < 4; ++rr)
#pragma unroll
                for (int q = 0; q < 8; ++q)
                    P[rr][q] = pk2(sE[(i0 + rr) * L + 2 * q],
                                   sE[(i0 + rr) * L + 2 * q + 1]);
            s01 = pk2(1.f, 1.f); s23 = pk2(1.f, 1.f);
            half_recursion<false>(xg, P, cnt, baseRow, kMax, s01, s23, M);
        }

        __syncthreads();

        if (!isFwd) {
            u64 d01 = mul2(s01, sF01[slot]);
            u64 d23 = mul2(s23, sF23[slot]);
            float p = hadd2(d01) + hadd2(d23);
            p += __shfl_xor_sync(FULL, p, 1, 4);
            p += __shfl_xor_sync(FULL, p, 2, 4);
            float z = __logf(p) + M + sMf[slot];
            if (c == 0) out[b] = z - sScore[slot];
        }
    } else {
        // emit + transition score warps
        int we = w - 8;
#pragma unroll 1
        for (int k = 0; k < 8; ++k) {
            int slot = we * 8 + k;
            int b = min(blockBase + slot, B - 1);
            const int*   lb = label + (size_t)b * T;
            const float* xb = x + (size_t)b * T * L;
            int len = length[b];

            float acc = 0.f;
            for (int t = lane; t < len; t += 32) {
                int lab = lb[t];
                acc += xb[t * L + lab];
                if (t >= 1) acc += sT[lb[t - 1] * L + lab];
            }
            acc += __shfl_xor_sync(FULL, acc, 16);
            acc += __shfl_xor_sync(FULL, acc, 8);
            acc += __shfl_xor_sync(FULL, acc, 4);
            acc += __shfl_xor_sync(FULL, acc, 2);
            acc += __shfl_xor_sync(FULL, acc, 1);
            if (lane == 0) sScore[slot] = acc;
        }
        __syncthreads();
    }
}

extern "C" void kernel_launch(void* const* d_in, const int* in_sizes, int n_in,
                              void* d_out, int out_size) {
    const float* x      = (const float*)d_in[0];
    const float* trans  = (const float*)d_in[1];
    const int*   label  = (const int*)d_in[2];
    const int*   length = (const int*)d_in[3];
    float*       out    = (float*)d_out;

    int B = in_sizes[3];                 // 4096
    int T = in_sizes[2] / B;             // 512

    int grid = (B + 31) / 32;            // 32 batches per block
    crf_kernel<<<grid, 384>>>(x, trans, label, length, out, B, T);
}

// round 4
// speedup vs baseline: 2.3981x; 1.0890x over previous
#include <cuda_runtime.h>

#define FULL 0xffffffffu
typedef unsigned long long u64;

constexpr int L = 16;
constexpr float LOG2E = 1.4426950408889634f;
constexpr float LN2   = 0.6931471805599453f;

__device__ __forceinline__ u64 pk2(float lo, float hi) {
    u64 r; asm("mov.b64 %0,{%1,%2};" : "=l"(r) : "f"(lo), "f"(hi)); return r;
}
__device__ __forceinline__ void upk2(u64 v, float& lo, float& hi) {
    asm("mov.b64 {%0,%1},%2;" : "=f"(lo), "=f"(hi) : "l"(v));
}
__device__ __forceinline__ u64 fma2(u64 a, u64 b, u64 c) {
    u64 d; asm("fma.rn.f32x2 %0,%1,%2,%3;" : "=l"(d) : "l"(a), "l"(b), "l"(c)); return d;
}
__device__ __forceinline__ u64 mul2(u64 a, u64 b) {
    u64 d; asm("mul.rn.f32x2 %0,%1,%2;" : "=l"(d) : "l"(a), "l"(b)); return d;
}
__device__ __forceinline__ float ex2f(float v) {
    float r; asm("ex2.approx.f32 %0,%1;" : "=f"(r) : "f"(v)); return r;
}
__device__ __forceinline__ float hadd2(u64 v) {
    float lo, hi; upk2(v, lo, hi); return lo + hi;
}
__device__ __forceinline__ u64 shfl64_4(u64 v, int src) {
    unsigned lo = (unsigned)v, hi = (unsigned)(v >> 32);
    lo = __shfl_sync(FULL, lo, src, 4);
    hi = __shfl_sync(FULL, hi, src, 4);
    return ((u64)hi << 32) | lo;
}

// one matvec: out_j = sum_i u_i * P-pair layout, for this lane's 4 outputs
__device__ __forceinline__ void matvec4(const u64 (&P)[4][8], u64 m01, u64 m23,
                                        float& o0, float& o1, float& o2, float& o3) {
    u64 v[8];
#pragma unroll
    for (int g4 = 0; g4 < 4; ++g4) {
        v[2 * g4]     = shfl64_4(m01, g4);
        v[2 * g4 + 1] = shfl64_4(m23, g4);
    }
    u64 a0 = 0, a1 = 0, a2 = 0, a3 = 0;
#pragma unroll
    for (int q = 0; q < 8; ++q) {
        a0 = fma2(v[q], P[0][q], a0);
        a1 = fma2(v[q], P[1][q], a1);
        a2 = fma2(v[q], P[2][q], a2);
        a3 = fma2(v[q], P[3][q], a3);
    }
    o0 = hadd2(a0); o1 = hadd2(a1); o2 = hadd2(a2); o3 = hadd2(a3);
}

// Unified segment recursion (fwd and bwd have identical step shape):
//   s' = e_row(k) .* matvec(P, s)
// rows: base + dir*k, k = 0..cnt-1, clamped reads, padded trip count.
__device__ __forceinline__ void seg_recursion(
    const float* __restrict__ xg, const u64 (&P)[4][8],
    int cnt, int base, int dir, int kMaxPad,
    u64& s01, u64& s23, int& Msum)
{
    int cl = max(cnt - 1, 0);

    float4 xv[4];
#pragma unroll
    for (int d = 0; d < 4; ++d) {
        int row = max(base + dir * min(d, cl), 0);
        xv[d] = *(const float4*)(xg + (size_t)row * L);
    }
    float e0 = ex2f(xv[0].x * LOG2E), e1 = ex2f(xv[0].y * LOG2E);
    float e2 = ex2f(xv[0].z * LOG2E), e3 = ex2f(xv[0].w * LOG2E);

    for (int k0 = 0; k0 < kMaxPad; k0 += 4) {
#pragma unroll
        for (int kk = 0; kk < 4; ++kk) {
            int k = k0 + kk;

            // prefetch row k+4 into the slot being vacated
            int row = max(base + dir * min(k + 4, cl), 0);
            float4 xn = *(const float4*)(xg + (size_t)row * L);

            float o0, o1, o2, o3;
            matvec4(P, s01, s23, o0, o1, o2, o3);

            // e for next step, from xv[(k+1)&3] (loaded 3 iters ago)
            float4 xe = xv[(kk + 1) & 3];
            float n0 = ex2f(xe.x * LOG2E), n1 = ex2f(xe.y * LOG2E);
            float n2 = ex2f(xe.z * LOG2E), n3 = ex2f(xe.w * LOG2E);
            xv[kk] = xn;

            u64 t01 = pk2(o0 * e0, o1 * e1);
            u64 t23 = pk2(o2 * e2, o3 * e3);
            bool act = k < cnt;
            if (act) { s01 = t01; s23 = t23; }
            e0 = n0; e1 = n1; e2 = n2; e3 = n3;

            if ((k & 7) == 7) {       // exponent-only rescale, integer accumulator
                u64 p0 = shfl64_4(s01, 0);
                float s0, sd; upk2(p0, s0, sd);
                int ee = (__float_as_int(s0) >> 23) - 127;
                if (act) {
                    Msum += ee;
                    float sc = __int_as_float((127 - ee) << 23);
                    u64 sc2 = pk2(sc, sc);
                    s01 = mul2(s01, sc2);
                    s23 = mul2(s23, sc2);
                }
            }
        }
    }
}

// Block = 384 threads = 12 warps, 32 batches:
//  warps 0-3: forward halves (8 batches each), 4-7: backward halves, 8-11: emit.
__global__ __launch_bounds__(384, 1) void crf_kernel(
    const float* __restrict__ x, const float* __restrict__ trans,
    const int* __restrict__ label, const int* __restrict__ length,
    float* __restrict__ out, int B, int T)
{
    __shared__ float sE[L * L];
    __shared__ float sT[L * L];
    __shared__ float sScore[32];
    __shared__ u64   sF01[32], sF23[32];
    __shared__ int   sM[32];

    int tid  = threadIdx.x;
    int lane = tid & 31;
    int w    = tid >> 5;

    if (tid < L * L) {
        float tv = trans[tid];
        sT[tid] = tv;
        sE[tid] = ex2f(tv * LOG2E);
    }
    __syncthreads();

    int blockBase = blockIdx.x * 32;

    // registers persisting to after the barrier (bwd warps)
    u64 w01 = 0, w23 = 0;
    int Msum = 0;
    int slot = 0, b = 0, c = lane & 3;
    int len = 1;

    if (w < 8) {
        bool isFwd = w < 4;
        int wb = isFwd ? w : w - 4;
        int g  = lane >> 2;
        slot = wb * 8 + g;
        b    = min(blockBase + slot, B - 1);

        const float* xg = x + (size_t)b * T * L + c * 4;
        len = length[b];
        int m = (len - 1) >> 1;

        int cnt  = isFwd ? m : max(len - 2 - m, 0);
        int base = isFwd ? 1 : (len - 2);
        int dir  = isFwd ? 1 : -1;

        int kMax = cnt;
        kMax = max(kMax, __shfl_xor_sync(FULL, kMax, 4));
        kMax = max(kMax, __shfl_xor_sync(FULL, kMax, 8));
        kMax = max(kMax, __shfl_xor_sync(FULL, kMax, 16));
        int kMaxPad = (kMax + 3) & ~3;

        u64 P[4][8];
        if (isFwd) {
            int j0 = 4 * c;
#pragma unroll
            for (int cc = 0; cc < 4; ++cc)
#pragma unroll
                for (int q = 0; q < 8; ++q)
                    P[cc][q] = pk2(sE[(2 * q) * L + j0 + cc],
                                   sE[(2 * q + 1) * L + j0 + cc]);
        } else {
            int i0 = 4 * c;
#pragma unroll
            for (int rr = 0; rr < 4; ++rr)
#pragma unroll
                for (int q = 0; q < 8; ++q)
                    P[rr][q] = pk2(sE[(i0 + rr) * L + 2 * q],
                                   sE[(i0 + rr) * L + 2 * q + 1]);
        }

        // init: exp of row 0 (fwd) / row len-1 (bwd)
        int initRow = isFwd ? 0 : (len - 1);
        float4 x0 = *(const float4*)(xg + (size_t)initRow * L);
        u64 s01 = pk2(ex2f(x0.x * LOG2E), ex2f(x0.y * LOG2E));
        u64 s23 = pk2(ex2f(x0.z * LOG2E), ex2f(x0.w * LOG2E));

        seg_recursion(xg, P, cnt, base, dir, kMaxPad, s01, s23, Msum);

        if (isFwd) {
            sF01[slot] = s01; sF23[slot] = s23; sM[slot] = Msum;
        } else {
            // final plain matvec: w_m = E * wtilde_{m+1}
            float o0, o1, o2, o3;
            matvec4(P, s01, s23, o0, o1, o2, o3);
            w01 = pk2(o0, o1); w23 = pk2(o2, o3);
            if (len == 1) { w01 = pk2(1.f, 1.f); w23 = pk2(1.f, 1.f); }
        }
    } else {
        // emit + transition score warps
        int we = w - 8;
#pragma unroll 1
        for (int k = 0; k < 8; ++k) {
            int sl = we * 8 + k;
            int bb = min(blockBase + sl, B - 1);
            const int*   lb = label + (size_t)bb * T;
            const float* xb = x + (size_t)bb * T * L;
            int ll = length[bb];

            float acc = 0.f;
            for (int t = lane; t < ll; t += 32) {
                int lab = lb[t];
                acc += xb[t * L + lab];
                if (t >= 1) acc += sT[lb[t - 1] * L + lab];
            }
            acc += __shfl_xor_sync(FULL, acc, 16);
            acc += __shfl_xor_sync(FULL, acc, 8);
            acc += __shfl_xor_sync(FULL, acc, 4);
            acc += __shfl_xor_sync(FULL, acc, 2);
            acc += __shfl_xor_sync(FULL, acc, 1);
            if (lane == 0) sScore[sl] = acc;
        }
    }

    __syncthreads();   // single convergent barrier

    if (w >= 4 && w < 8) {
        float p = hadd2(mul2(w01, sF01[slot])) + hadd2(mul2(w23, sF23[slot]));
        p += __shfl_xor_sync(FULL, p, 1, 4);
        p += __shfl_xor_sync(FULL, p, 2, 4);
        float z = __logf(p) + (float)(Msum + sM[slot]) * LN2;
        if (c == 0) out[b] = z - sScore[slot];
    }
}

extern "C" void kernel_launch(void* const* d_in, const int* in_sizes, int n_in,
                              void* d_out, int out_size) {
    const float* x      = (const float*)d_in[0];
    const float* trans  = (const float*)d_in[1];
    const int*   label  = (const int*)d_in[2];
    const int*   length = (const int*)d_in[3];
    float*       out    = (float*)d_out;

    int B = in_sizes[3];                 // 4096
    int T = in_sizes[2] / B;             // 512

    int grid = (B + 31) / 32;            // 32 batches per block
    crf_kernel<<<grid, 384>>>(x, trans, label, length, out, B, T);
}

// round 5
// speedup vs baseline: 2.5234x; 1.0523x over previous
#include <cuda_runtime.h>

#define FULL 0xffffffffu
typedef unsigned long long u64;

constexpr int L = 16;
constexpr float LOG2E = 1.4426950408889634f;
constexpr float LN2   = 0.6931471805599453f;

__device__ __forceinline__ u64 pk2(float lo, float hi) {
    u64 r; asm("mov.b64 %0,{%1,%2};" : "=l"(r) : "f"(lo), "f"(hi)); return r;
}
__device__ __forceinline__ void upk2(u64 v, float& lo, float& hi) {
    asm("mov.b64 {%0,%1},%2;" : "=f"(lo), "=f"(hi) : "l"(v));
}
__device__ __forceinline__ u64 fma2(u64 a, u64 b, u64 c) {
    u64 d; asm("fma.rn.f32x2 %0,%1,%2,%3;" : "=l"(d) : "l"(a), "l"(b), "l"(c)); return d;
}
__device__ __forceinline__ u64 mul2(u64 a, u64 b) {
    u64 d; asm("mul.rn.f32x2 %0,%1,%2;" : "=l"(d) : "l"(a), "l"(b)); return d;
}
__device__ __forceinline__ float ex2f(float v) {
    float r; asm("ex2.approx.f32 %0,%1;" : "=f"(r) : "f"(v)); return r;
}
__device__ __forceinline__ float hadd2(u64 v) {
    float lo, hi; upk2(v, lo, hi); return lo + hi;
}
__device__ __forceinline__ u64 shflx1(u64 v) {
    unsigned lo = (unsigned)v, hi = (unsigned)(v >> 32);
    lo = __shfl_xor_sync(FULL, lo, 1);
    hi = __shfl_xor_sync(FULL, hi, 1);
    return ((u64)hi << 32) | lo;
}
__device__ __forceinline__ u64 shfl_idx64(u64 v, int src) {
    unsigned lo = (unsigned)v, hi = (unsigned)(v >> 32);
    lo = __shfl_sync(FULL, lo, src);
    hi = __shfl_sync(FULL, hi, src);
    return ((u64)hi << 32) | lo;
}

// 16x16 matvec for 8-states-per-lane, 2 lanes per segment (partner = lane^1).
// v = [own 4 u64 pairs, partner 4 u64 pairs]; P is pre-permuted to match.
__device__ __forceinline__ void matvec8(const u64 (&P)[8][8], const u64 (&s)[4],
                                        float (&o)[8]) {
    u64 v[8];
    v[0] = s[0]; v[1] = s[1]; v[2] = s[2]; v[3] = s[3];
    v[4] = shflx1(s[0]); v[5] = shflx1(s[1]);
    v[6] = shflx1(s[2]); v[7] = shflx1(s[3]);
#pragma unroll
    for (int r = 0; r < 8; ++r) {
        u64 a = 0;
#pragma unroll
        for (int q = 0; q < 8; ++q) a = fma2(v[q], P[r][q], a);
        o[r] = hadd2(a);
    }
}

// Block = 256 threads = 8 warps, 32 batches:
//  warps 0-3: recursion, 8 batches each; per 4-lane group: lanes (sub0,sub1)=fwd
//             halves (states 0-7 / 8-15), (sub2,sub3)=bwd halves.
//  warps 4-7: emit + transition scores, 8 batches each.
// Grid = B/32 = 128 -> 1 block/SM, one recursion warp per SMSP.
__global__ __launch_bounds__(256, 1) void crf_kernel(
    const float* __restrict__ x, const float* __restrict__ trans,
    const int* __restrict__ label, const int* __restrict__ length,
    float* __restrict__ out, int B, int T)
{
    __shared__ float sE[L * L];
    __shared__ float sT[L * L];
    __shared__ float sScore[32];

    int tid  = threadIdx.x;
    int lane = tid & 31;
    int w    = tid >> 5;

    if (tid < L * L) {
        float tv = trans[tid];
        sT[tid] = tv;
        sE[tid] = ex2f(tv * LOG2E);
    }
    __syncthreads();

    int blockBase = blockIdx.x * 32;

    if (w < 4) {
        // ---------------- recursion warps ----------------
        int g    = lane >> 2;        // batch slot in warp (0..7)
        int sub  = lane & 3;         // 0,1 fwd ; 2,3 bwd
        int half = sub & 1;          // state half: 0 -> states 0-7, 1 -> 8-15
        bool isBwd = sub >= 2;
        int slot = w * 8 + g;
        int b    = blockBase + slot;

        const float4* px = (const float4*)(x + (size_t)b * T * L);
        int len = length[b];
        int m   = (len - 1) >> 1;

        int cnt  = isBwd ? max(len - 2 - m, 0) : m;
        int base = isBwd ? (len - 2) : 1;
        int dir  = isBwd ? -1 : 1;
        int cl   = max(cnt - 1, 0);

        int kMax = cnt;
#pragma unroll
        for (int o = 1; o <= 16; o <<= 1)
            kMax = max(kMax, __shfl_xor_sync(FULL, kMax, o));
        int kMaxPad = (kMax + 3) & ~3;

        // Build P (pre-permuted so v = [own pairs, partner pairs]).
        int b8 = 8 * half;
        u64 P[8][8];
#pragma unroll
        for (int r = 0; r < 8; ++r)
#pragma unroll
            for (int q = 0; q < 8; ++q) {
                int gq = (q < 4) ? (4 * half + q) : (4 * (1 - half) + q - 4);
                float lo, hi;
                if (!isBwd) {  // columns j = b8+r
                    lo = sE[(2 * gq) * L + b8 + r];
                    hi = sE[(2 * gq + 1) * L + b8 + r];
                } else {       // rows i = b8+r
                    lo = sE[(b8 + r) * L + 2 * gq];
                    hi = sE[(b8 + r) * L + 2 * gq + 1];
                }
                P[r][q] = pk2(lo, hi);
            }

        // init: fwd s = exp(x_0), bwd q = exp(x_{len-1})
        int initRow = isBwd ? (len - 1) : 0;
        {
            const float4* pr = px + (size_t)initRow * 4 + 2 * half;
            float4 iA = pr[0], iB = pr[1];
            // placeholder; real init below after declaring s
        }

        u64 s[4];
        {
            const float4* pr = px + (size_t)initRow * 4 + 2 * half;
            float4 iA = pr[0], iB = pr[1];
            s[0] = pk2(ex2f(iA.x * LOG2E), ex2f(iA.y * LOG2E));
            s[1] = pk2(ex2f(iA.z * LOG2E), ex2f(iA.w * LOG2E));
            s[2] = pk2(ex2f(iB.x * LOG2E), ex2f(iB.y * LOG2E));
            s[3] = pk2(ex2f(iB.z * LOG2E), ex2f(iB.w * LOG2E));
        }
        int Msum = 0;

        // prefetch ring of x rows (clamped indices)
        float4 xA[4], xB[4];
#pragma unroll
        for (int d = 0; d < 4; ++d) {
            int row = max(base + dir * min(d, cl), 0);
            const float4* pr = px + (size_t)row * 4 + 2 * half;
            xA[d] = pr[0]; xB[d] = pr[1];
        }
        float e[8];
        e[0] = ex2f(xA[0].x * LOG2E); e[1] = ex2f(xA[0].y * LOG2E);
        e[2] = ex2f(xA[0].z * LOG2E); e[3] = ex2f(xA[0].w * LOG2E);
        e[4] = ex2f(xB[0].x * LOG2E); e[5] = ex2f(xB[0].y * LOG2E);
        e[6] = ex2f(xB[0].z * LOG2E); e[7] = ex2f(xB[0].w * LOG2E);

        for (int k0 = 0; k0 < kMaxPad; k0 += 4) {
#pragma unroll
            for (int kk = 0; kk < 4; ++kk) {
                int k = k0 + kk;

                int rowN = max(base + dir * min(k + 4, cl), 0);
                const float4* pr = px + (size_t)rowN * 4 + 2 * half;
                float4 nA = pr[0], nB = pr[1];

                float o[8];
                matvec8(P, s, o);

                // e for next step (row k+1, loaded 3 iterations ago)
                float4 eA = xA[(kk + 1) & 3], eB = xB[(kk + 1) & 3];
                float n0 = ex2f(eA.x * LOG2E), n1 = ex2f(eA.y * LOG2E);
                float n2 = ex2f(eA.z * LOG2E), n3 = ex2f(eA.w * LOG2E);
                float n4 = ex2f(eB.x * LOG2E), n5 = ex2f(eB.y * LOG2E);
                float n6 = ex2f(eB.z * LOG2E), n7 = ex2f(eB.w * LOG2E);
                xA[kk] = nA; xB[kk] = nB;

                u64 t0 = pk2(o[0] * e[0], o[1] * e[1]);
                u64 t1 = pk2(o[2] * e[2], o[3] * e[3]);
                u64 t2 = pk2(o[4] * e[4], o[5] * e[5]);
                u64 t3 = pk2(o[6] * e[6], o[7] * e[7]);

                bool act = k < cnt;
                if (act) { s[0] = t0; s[1] = t1; s[2] = t2; s[3] = t3; }
                e[0] = n0; e[1] = n1; e[2] = n2; e[3] = n3;
                e[4] = n4; e[5] = n5; e[6] = n6; e[7] = n7;

                if ((k & 7) == 7) {   // exponent-only rescale by batch state 0
                    unsigned r32 = __shfl_sync(FULL, (unsigned)s[0], lane & ~1);
                    int ee = ((int)(r32 >> 23) & 0xff) - 127;
                    if (act) {
                        Msum += ee;
                        float sc = __int_as_float((127 - ee) << 23);
                        u64 sc2 = pk2(sc, sc);
                        s[0] = mul2(s[0], sc2); s[1] = mul2(s[1], sc2);
                        s[2] = mul2(s[2], sc2); s[3] = mul2(s[3], sc2);
                    }
                }
            }
        }

        // final plain matvec for bwd: beta_m = E * q_{m+1} (run by all lanes,
        // fwd lanes discard). len==1 -> beta = ones.
        {
            float o[8];
            matvec8(P, s, o);
            if (isBwd) {
                if (len == 1) {
                    s[0] = s[1] = s[2] = s[3] = pk2(1.f, 1.f);
                } else {
                    s[0] = pk2(o[0], o[1]); s[1] = pk2(o[2], o[3]);
                    s[2] = pk2(o[4], o[5]); s[3] = pk2(o[6], o[7]);
                }
            }
        }

        __syncthreads();   // emit scores ready

        // combine: fwd lanes dot with partner bwd lanes (same half)
        int srcW = (lane & ~3) + 2 + half;
        u64 w0 = shfl_idx64(s[0], srcW), w1 = shfl_idx64(s[1], srcW);
        u64 w2 = shfl_idx64(s[2], srcW), w3 = shfl_idx64(s[3], srcW);
        float p = hadd2(mul2(s[0], w0)) + hadd2(mul2(s[1], w1))
                + hadd2(mul2(s[2], w2)) + hadd2(mul2(s[3], w3));
        p += __shfl_xor_sync(FULL, p, 1);
        int Mb = __shfl_sync(FULL, Msum, srcW);
        float z = __logf(p) + (float)(Msum + Mb) * LN2;
        if (sub == 0) out[b] = z - sScore[slot];
    } else {
        // ---------------- emit / transition warps ----------------
        int we = w - 4;
#pragma unroll 1
        for (int k2 = 0; k2 < 8; ++k2) {
            int sl = we * 8 + k2;
            int bb = blockBase + sl;
            const int*   lb = label + (size_t)bb * T;
            const float* xb = x + (size_t)bb * T * L;
            int ll = length[bb];

            float acc = 0.f;
            for (int t = lane; t < ll; t += 32) {
                int lab = lb[t];
                acc += __ldg(xb + t * L + lab);
                if (t >= 1) acc += sT[lb[t - 1] * L + lab];
            }
            acc += __shfl_xor_sync(FULL, acc, 16);
            acc += __shfl_xor_sync(FULL, acc, 8);
            acc += __shfl_xor_sync(FULL, acc, 4);
            acc += __shfl_xor_sync(FULL, acc, 2);
            acc += __shfl_xor_sync(FULL, acc, 1);
            if (lane == 0) sScore[sl] = acc;
        }
        __syncthreads();
    }
}

extern "C" void kernel_launch(void* const* d_in, const int* in_sizes, int n_in,
                              void* d_out, int out_size) {
    const float* x      = (const float*)d_in[0];
    const float* trans  = (const float*)d_in[1];
    const int*   label  = (const int*)d_in[2];
    const int*   length = (const int*)d_in[3];
    float*       out    = (float*)d_out;

    int B = in_sizes[3];                 // 4096
    int T = in_sizes[2] / B;             // 512

    int grid = (B + 31) / 32;            // 32 batches per block, 128 blocks
    crf_kernel<<<grid, 256>>>(x, trans, label, length, out, B, T);
}

// round 6
// speedup vs baseline: 4.3884x; 1.7391x over previous
#include <cuda_runtime.h>

#define FULL 0xffffffffu
typedef unsigned int u32;

constexpr int L = 16;
constexpr float LOG2E = 1.4426950408889634f;
constexpr float LN2   = 0.6931471805599453f;

__device__ __forceinline__ float ex2f(float v) {
    float r; asm("ex2.approx.f32 %0,%1;" : "=f"(r) : "f"(v)); return r;
}
// pack two f32 into bf16x2: hi<-a, lo<-b
__device__ __forceinline__ u32 pkbf(float hi, float lo) {
    u32 r; asm("cvt.rn.bf16x2.f32 %0,%1,%2;" : "=r"(r) : "f"(hi), "f"(lo)); return r;
}
__device__ __forceinline__ u32 mulbf2(u32 a, u32 b) {
    u32 r; asm("mul.rn.bf16x2 %0,%1,%2;" : "=r"(r) : "r"(a), "r"(b)); return r;
}
__device__ __forceinline__ float bflo(u32 v) { return __uint_as_float(v << 16); }
__device__ __forceinline__ float bfhi(u32 v) { return __uint_as_float(v & 0xffff0000u); }

__device__ __forceinline__ void mma16816(
    float& d0, float& d1, float& d2, float& d3,
    u32 a0, u32 a1, u32 a2, u32 a3, u32 b0, u32 b1)
{
    asm volatile(
        "mma.sync.aligned.m16n8k16.row.col.f32.bf16.bf16.f32 "
        "{%0,%1,%2,%3}, {%4,%5,%6,%7}, {%8,%9}, {%10,%11,%12,%13};"
        : "=f"(d0), "=f"(d1), "=f"(d2), "=f"(d3)
        : "r"(a0), "r"(a1), "r"(a2), "r"(a3), "r"(b0), "r"(b1),
          "f"(0.f), "f"(0.f), "f"(0.f), "f"(0.f));
}

// Block = 256 threads = 8 warps, 32 batches:
//  warp 0: fwd batches 0-15, warp 1: fwd 16-31, warp 2: bwd 0-15, warp 3: bwd 16-31
//  warps 4-7: emit + transition scores (8 batches each)
// Recursion state s lives as the A-fragment (bf16) of m16n8k16; one step =
// two MMAs (cols 0-7, 8-15) -> D(fp32) -> *exp(x_t) -> bf16 -> next A.
__global__ __launch_bounds__(256, 1) void crf_kernel(
    const float* __restrict__ x, const float* __restrict__ trans,
    const int* __restrict__ label, const int* __restrict__ length,
    float* __restrict__ out, int B, int T)
{
    __shared__ float sE[L * L];
    __shared__ float sT[L * L];
    __shared__ u32   sFA[2][32][4];   // fwd final A-fragments
    __shared__ int   sMf[2][16];      // fwd exponent accumulators per batch
    __shared__ float sScore[32];

    int tid  = threadIdx.x;
    int lane = tid & 31;
    int w    = tid >> 5;
    int g    = lane >> 2;     // row group: rows g and g+8 (= batches)
    int tig  = lane & 3;

    if (tid < L * L) {
        float tv = trans[tid];
        sT[tid] = tv;
        sE[tid] = tv * LOG2E;   // store in log2 domain; exp built below
    }
    __syncthreads();

    int blockBase = blockIdx.x * 32;

    if (w < 4) {
        bool isBwd = w >= 2;
        int grp = w & 1;
        int bBase = blockBase + grp * 16;
        int b_lo = bBase + g, b_hi = bBase + g + 8;
        int lenL = length[b_lo], lenH = length[b_hi];
        int mL = (lenL - 1) >> 1, mH = (lenH - 1) >> 1;
        int cntL = isBwd ? max(lenL - 2 - mL, 0) : mL;
        int cntH = isBwd ? max(lenH - 2 - mH, 0) : mH;
        int baseL = isBwd ? (lenL - 2) : 1;
        int baseH = isBwd ? (lenH - 2) : 1;
        int dir   = isBwd ? -1 : 1;
        int clL = max(cntL - 1, 0), clH = max(cntH - 1, 0);

        int kMax = max(cntL, cntH);
#pragma unroll
        for (int o = 1; o <= 16; o <<= 1)
            kMax = max(kMax, __shfl_xor_sync(FULL, kMax, o));
        int kMaxPad = (kMax + 3) & ~3;

        // B fragments (constant): fwd B[k][n]=E[k][n]; bwd B[k][n]=E[n][k]
        u32 b00, b01, b10, b11;
        {
            int k0 = tig * 2;
            float e00, e01, e02, e03, e10, e11, e12, e13;
            if (!isBwd) {
                e00 = sE[k0 * L + g];       e01 = sE[(k0 + 1) * L + g];
                e02 = sE[(k0 + 8) * L + g]; e03 = sE[(k0 + 9) * L + g];
                e10 = sE[k0 * L + g + 8];       e11 = sE[(k0 + 1) * L + g + 8];
                e12 = sE[(k0 + 8) * L + g + 8]; e13 = sE[(k0 + 9) * L + g + 8];
            } else {
                e00 = sE[g * L + k0];       e01 = sE[g * L + k0 + 1];
                e02 = sE[g * L + k0 + 8];   e03 = sE[g * L + k0 + 9];
                e10 = sE[(g + 8) * L + k0];     e11 = sE[(g + 8) * L + k0 + 1];
                e12 = sE[(g + 8) * L + k0 + 8]; e13 = sE[(g + 8) * L + k0 + 9];
            }
            b00 = pkbf(ex2f(e01), ex2f(e00));
            b01 = pkbf(ex2f(e03), ex2f(e02));
            b10 = pkbf(ex2f(e11), ex2f(e10));
            b11 = pkbf(ex2f(e13), ex2f(e12));
        }

        const float* pL = x + (size_t)b_lo * T * L + tig * 2;
        const float* pH = x + (size_t)b_hi * T * L + tig * 2;

        // init: s = exp(x at row 0 (fwd) / len-1 (bwd))
        int irL = isBwd ? (lenL - 1) : 0;
        int irH = isBwd ? (lenH - 1) : 0;
        float2 iLa = *(const float2*)(pL + (size_t)irL * L);
        float2 iLb = *(const float2*)(pL + (size_t)irL * L + 8);
        float2 iHa = *(const float2*)(pH + (size_t)irH * L);
        float2 iHb = *(const float2*)(pH + (size_t)irH * L + 8);
        u32 A0 = pkbf(ex2f(iLa.y * LOG2E), ex2f(iLa.x * LOG2E));
        u32 A1 = pkbf(ex2f(iHa.y * LOG2E), ex2f(iHa.x * LOG2E));
        u32 A2 = pkbf(ex2f(iLb.y * LOG2E), ex2f(iLb.x * LOG2E));
        u32 A3 = pkbf(ex2f(iHb.y * LOG2E), ex2f(iHb.x * LOG2E));
        int MsL = 0, MsH = 0;

        // 4-deep prefetch ring of x rows (clamped)
        float2 rLa[4], rLb[4], rHa[4], rHb[4];
#pragma unroll
        for (int d = 0; d < 4; ++d) {
            int rowL = max(baseL + dir * min(d, clL), 0);
            int rowH = max(baseH + dir * min(d, clH), 0);
            rLa[d] = *(const float2*)(pL + (size_t)rowL * L);
            rLb[d] = *(const float2*)(pL + (size_t)rowL * L + 8);
            rHa[d] = *(const float2*)(pH + (size_t)rowH * L);
            rHb[d] = *(const float2*)(pH + (size_t)rowH * L + 8);
        }

        for (int k0 = 0; k0 < kMaxPad; k0 += 4) {
#pragma unroll
            for (int kk = 0; kk < 4; ++kk) {
                int k = k0 + kk;

                float2 xLa = rLa[kk], xLb = rLb[kk];
                float2 xHa = rHa[kk], xHb = rHb[kk];

                float eL0 = ex2f(xLa.x * LOG2E), eL1 = ex2f(xLa.y * LOG2E);
                float eL2 = ex2f(xLb.x * LOG2E), eL3 = ex2f(xLb.y * LOG2E);
                float eH0 = ex2f(xHa.x * LOG2E), eH1 = ex2f(xHa.y * LOG2E);
                float eH2 = ex2f(xHb.x * LOG2E), eH3 = ex2f(xHb.y * LOG2E);

                float d0, d1, d2, d3, f0, f1, f2, f3;
                mma16816(d0, d1, d2, d3, A0, A1, A2, A3, b00, b01);
                mma16816(f0, f1, f2, f3, A0, A1, A2, A3, b10, b11);

                // refill ring slot with row k+4
                {
                    int rowL = max(baseL + dir * min(k + 4, clL), 0);
                    int rowH = max(baseH + dir * min(k + 4, clH), 0);
                    rLa[kk] = *(const float2*)(pL + (size_t)rowL * L);
                    rLb[kk] = *(const float2*)(pL + (size_t)rowL * L + 8);
                    rHa[kk] = *(const float2*)(pH + (size_t)rowH * L);
                    rHb[kk] = *(const float2*)(pH + (size_t)rowH * L + 8);
                }

                u32 n0 = pkbf(d1 * eL1, d0 * eL0);   // row g,   cols 0-7 pair
                u32 n1 = pkbf(d3 * eH1, d2 * eH0);   // row g+8, cols 0-7 pair
                u32 n2 = pkbf(f1 * eL3, f0 * eL2);   // row g,   cols 8-15
                u32 n3 = pkbf(f3 * eH3, f2 * eH2);   // row g+8, cols 8-15

                bool aL = k < cntL, aH = k < cntH;
                A0 = aL ? n0 : A0;  A2 = aL ? n2 : A2;
                A1 = aH ? n1 : A1;  A3 = aH ? n3 : A3;

                if ((k & 7) == 7) {   // exponent-only rescale per batch row
                    u32 s0 = __shfl_sync(FULL, A0, lane & ~3);
                    u32 s1 = __shfl_sync(FULL, A1, lane & ~3);
                    int eeL = (int)((s0 >> 7) & 0xff) - 127;
                    int eeH = (int)((s1 >> 7) & 0xff) - 127;
                    u32 hL = (u32)(127 - eeL) << 7;
                    u32 hH = (u32)(127 - eeH) << 7;
                    u32 scL = aL ? (hL | (hL << 16)) : 0x3f803f80u;
                    u32 scH = aH ? (hH | (hH << 16)) : 0x3f803f80u;
                    MsL += aL ? eeL : 0;
                    MsH += aH ? eeH : 0;
                    A0 = mulbf2(A0, scL); A2 = mulbf2(A2, scL);
                    A1 = mulbf2(A1, scH); A3 = mulbf2(A3, scH);
                }
            }
        }

        if (!isBwd) {
            sFA[grp][lane][0] = A0; sFA[grp][lane][1] = A1;
            sFA[grp][lane][2] = A2; sFA[grp][lane][3] = A3;
            if (tig == 0) { sMf[grp][g] = MsL; sMf[grp][g + 8] = MsH; }
            __syncthreads();
        } else {
            // beta_m = E * q~ : one more (plain) double-MMA
            float d0, d1, d2, d3, f0, f1, f2, f3;
            mma16816(d0, d1, d2, d3, A0, A1, A2, A3, b00, b01);
            mma16816(f0, f1, f2, f3, A0, A1, A2, A3, b10, b11);
            if (lenL == 1) { d0 = d1 = 1.f; f0 = f1 = 1.f; }
            if (lenH == 1) { d2 = d3 = 1.f; f2 = f3 = 1.f; }

            __syncthreads();

            u32 a0 = sFA[grp][lane][0], a1 = sFA[grp][lane][1];
            u32 a2 = sFA[grp][lane][2], a3 = sFA[grp][lane][3];
            float pLo = d0 * bflo(a0) + d1 * bfhi(a0) + f0 * bflo(a2) + f1 * bfhi(a2);
            float pHi = d2 * bflo(a1) + d3 * bfhi(a1) + f2 * bflo(a3) + f3 * bfhi(a3);
            pLo += __shfl_xor_sync(FULL, pLo, 1);
            pLo += __shfl_xor_sync(FULL, pLo, 2);
            pHi += __shfl_xor_sync(FULL, pHi, 1);
            pHi += __shfl_xor_sync(FULL, pHi, 2);
            float zL = __logf(pLo) + (float)(MsL + sMf[grp][g]) * LN2;
            float zH = __logf(pHi) + (float)(MsH + sMf[grp][g + 8]) * LN2;
            if (tig == 0) {
                out[b_lo] = zL - sScore[grp * 16 + g];
                out[b_hi] = zH - sScore[grp * 16 + g + 8];
            }
        }
    } else {
        // ---------------- emit / transition warps ----------------
        int we = w - 4;
#pragma unroll 1
        for (int k2 = 0; k2 < 8; ++k2) {
            int sl = we * 8 + k2;
            int bb = blockBase + sl;
            const int*   lb = label + (size_t)bb * T;
            const float* xb = x + (size_t)bb * T * L;
            int ll = length[bb];

            float acc = 0.f;
            for (int t = lane; t < ll; t += 32) {
                int lab = lb[t];
                acc += __ldg(xb + t * L + lab);
                if (t >= 1) acc += sT[lb[t - 1] * L + lab];
            }
            acc += __shfl_xor_sync(FULL, acc, 16);
            acc += __shfl_xor_sync(FULL, acc, 8);
            acc += __shfl_xor_sync(FULL, acc, 4);
            acc += __shfl_xor_sync(FULL, acc, 2);
            acc += __shfl_xor_sync(FULL, acc, 1);
            if (lane == 0) sScore[sl] = acc;
        }
        __syncthreads();
    }
}

extern "C" void kernel_launch(void* const* d_in, const int* in_sizes, int n_in,
                              void* d_out, int out_size) {
    const float* x      = (const float*)d_in[0];
    const float* trans  = (const float*)d_in[1];
    const int*   label  = (const int*)d_in[2];
    const int*   length = (const int*)d_in[3];
    float*       out    = (float*)d_out;

    int B = in_sizes[3];                 // 4096
    int T = in_sizes[2] / B;             // 512

    int grid = (B + 31) / 32;            // 32 batches per block, 128 blocks
    crf_kernel<<<grid, 256>>>(x, trans, label, length, out, B, T);
}